// round 8
// baseline (speedup 1.0000x reference)
#include <cuda_runtime.h>

#define S 1024
#define G 10
#define F 5
#define BB 8
#define CC 3
#define KW (2*F+1)
#define PX 4          // pixels per thread (x direction), lane-strided
#define TPB 128       // threads per block
#define SPAN (PX*TPB) // 512 output pixels per block row-segment

// ---------------------------------------------------------------------------
// Single fused kernel:
//   Stage A (block prologue): separable 11x11 edge-clamped Gaussian smoothing
//     of the 10x10 offset field, but only the 2 rows (iy0, iy1) this output
//     row needs. Rank-1 factorization: w2d[ky][kx] = w2d[ky][F]*w2d[F][kx]/w2d[F][F].
//     Then scale+clip and y-lerp into rowg[2*G].
//   Stage B: per-pixel field x-lerp, grid build, 4-corner bilinear gather of
//     3 channels. Lane-contiguous pixel mapping for ~128B gather footprints.
// ---------------------------------------------------------------------------
__global__ __launch_bounds__(TPB)
void deform_fused(const float* __restrict__ x,
                  const float* __restrict__ ox,
                  const float* __restrict__ oy,
                  const float* __restrict__ w,
                  const int*   __restrict__ mm_raw,
                  float* __restrict__ out)
{
    const int b   = blockIdx.z;
    const int y   = blockIdx.y;
    const int tid = threadIdx.x;

    __shared__ float t1[2][2][G];   // vertical-pass result [ch][rsel][col]
    __shared__ float s2[2][2][G];   // smoothed+clipped     [ch][rsel][col]
    __shared__ float rowg[2 * G];   // y-lerped field row   [ch*G + col]

    const float scale = (float)G / (float)S;   // exact
    const float hs    = 0.5f * scale - 0.5f;

    // y-interp coords for the 10x10 field (uniform across block)
    float sy  = fmaxf(fmaf((float)y, scale, hs), 0.0f);
    int   iy0 = min((int)sy, G - 1);
    int   iy1 = min(iy0 + 1, G - 1);
    float wy  = sy - (float)iy0;

    // ---- Stage A: separable smoothing of the 2 needed field rows ----
    if (tid < 40) {
        int ch   = tid / 20;            // 0 = x field, 1 = y field
        int rem  = tid - ch * 20;
        int rsel = rem / 10;            // 0 -> iy0 row, 1 -> iy1 row
        int j    = rem - rsel * 10;     // column 0..9
        int r    = rsel ? iy1 : iy0;

        // vertical 11-tap (clamped rows), weights = w2d[ky][F]
        const float* o = (ch ? oy : ox) + b * G * G + j;
        float acc = 0.0f;
        #pragma unroll
        for (int ky = 0; ky < KW; ky++) {
            int yy = min(max(r + ky - F, 0), G - 1);
            acc = fmaf(w[ky * KW + F], o[yy * G], acc);
        }
        t1[ch][rsel][j] = acc;
    }
    __syncthreads();
    if (tid < 40) {
        int ch   = tid / 20;
        int rem  = tid - ch * 20;
        int rsel = rem / 10;
        int j    = rem - rsel * 10;

        // horizontal 11-tap (clamped cols), weights = w2d[F][kx]
        float acc = 0.0f;
        #pragma unroll
        for (int kx = 0; kx < KW; kx++) {
            int xx = min(max(j + kx - F, 0), G - 1);
            acc = fmaf(w[F * KW + kx], t1[ch][rsel][xx], acc);
        }
        // decode max_move (int or float bits), fold /w2d[F][F] and *max_offset
        int   mi = mm_raw[0];
        float max_move = (mi > 0 && mi < 1000000) ? (float)mi : __int_as_float(mi);
        float max_offset = 2.0f * max_move / (float)S;
        acc *= max_offset / w[F * KW + F];
        acc  = fminf(fmaxf(acc, -max_offset), max_offset);
        s2[ch][rsel][j] = acc;
    }
    __syncthreads();
    if (tid < 2 * G) {
        int ch = tid / G;
        int j  = tid - ch * G;
        float a = s2[ch][0][j];
        float c = s2[ch][1][j];
        rowg[tid] = fmaf(c - a, wy, a);
    }
    __syncthreads();

    // ---- Stage B: per-pixel grid sample ----
    const float* rowgx = rowg;
    const float* rowgy = rowg + G;

    const int   xb  = blockIdx.x * SPAN;              // 0 or 512
    const float pxs = 2.0f / (float)(S - 1);
    const float pyv = fmaf((float)y, pxs, -1.0f);     // identity grid y

    const float* img = x   + (size_t)b * CC * S * S;
    float*       op  = out + (size_t)b * CC * S * S + (size_t)y * S
                           + xb + tid;

    float r[CC][PX];

    #pragma unroll
    for (int p = 0; p < PX; p++) {
        float xf = (float)(xb + p * TPB + tid);

        // field x-lerp from shared row
        float sx = fmaxf(fmaf(xf, scale, hs), 0.0f);
        int   j0 = min((int)sx, G - 1);
        int   j1 = min(j0 + 1, G - 1);
        float wx = sx - (float)j0;
        float ax0 = rowgx[j0], ax1 = rowgx[j1];
        float ay0 = rowgy[j0], ay1 = rowgy[j1];
        float gx = fmaf(ax1 - ax0, wx, ax0);
        float gy = fmaf(ay1 - ay0, wx, ay0);

        // identity grid + clip
        float g0 = fminf(fmaxf(gx + fmaf(xf, pxs, -1.0f), -1.0f), 1.0f);
        float g1 = fminf(fmaxf(gy + pyv, -1.0f), 1.0f);

        // source coords: ((g+1)*S-1)/2 = g*512 + 511.5, in [-0.5, 1023.5]
        float ixf = fmaf(g0, 512.0f, 511.5f);
        float iyf = fmaf(g1, 512.0f, 511.5f);

        float fx = floorf(ixf), fy = floorf(iyf);
        int x0 = (int)fx, y0 = (int)fy;      // in [-1, 1023]
        float axx = ixf - fx, ayy = iyf - fy;
        float omx = 1.0f - axx, omy = 1.0f - ayy;

        // only-reachable boundary masks
        float mx0 = (x0 >= 0)    ? 1.0f : 0.0f;
        float mx1 = (x0 < S - 1) ? 1.0f : 0.0f;
        float wy0 = (y0 >= 0)    ? omy  : 0.0f;
        float wy1 = (y0 < S - 1) ? ayy  : 0.0f;

        float w00 = wy0 * omx * mx0;
        float w01 = wy0 * axx * mx1;
        float w10 = wy1 * omx * mx0;
        float w11 = wy1 * axx * mx1;

        int xc0 = max(x0, 0);
        int xc1 = min(x0 + 1, S - 1);
        int yc0 = max(y0, 0) << 10;          // *S
        int yc1 = min(y0 + 1, S - 1) << 10;

        int o00 = yc0 + xc0, o01 = yc0 + xc1;
        int o10 = yc1 + xc0, o11 = yc1 + xc1;

        #pragma unroll
        for (int c = 0; c < CC; c++) {
            const float* im = img + (size_t)c * S * S;
            r[c][p] = w00 * __ldg(im + o00) + w01 * __ldg(im + o01)
                    + w10 * __ldg(im + o10) + w11 * __ldg(im + o11);
        }
    }

    // Coalesced stores: 128B warp footprint per store instruction.
    #pragma unroll
    for (int c = 0; c < CC; c++) {
        float* oc = op + (size_t)c * S * S;
        #pragma unroll
        for (int p = 0; p < PX; p++)
            oc[p * TPB] = r[c][p];
    }
}

extern "C" void kernel_launch(void* const* d_in, const int* in_sizes, int n_in,
                              void* d_out, int out_size)
{
    const float* x  = (const float*)d_in[0];
    const float* ox = (const float*)d_in[1];
    const float* oy = (const float*)d_in[2];
    const float* w  = (const float*)d_in[3];
    const int*   mm = (const int*)  d_in[4];

    dim3 blk(TPB, 1, 1);
    dim3 grd(S / SPAN, S, BB);   // 2 x 1024 x 8
    deform_fused<<<grd, blk>>>(x, ox, oy, w, mm, (float*)d_out);
}

// round 10
// speedup vs baseline: 1.0459x; 1.0459x over previous
#include <cuda_runtime.h>

#define S 1024
#define G 10
#define F 5
#define BB 8
#define CC 3
#define KW (2*F+1)
#define PX 4          // pixels per thread (x direction), lane-strided
#define TPB 128       // threads per block
#define SPAN (PX*TPB) // 512 output pixels per block row-segment

// Scratch for the smoothed, clipped offset field: (B, 2, G, G)
__device__ float g_smooth_dev[BB * 2 * G * G];

// ---------------------------------------------------------------------------
// Kernel 1: 11x11 edge-padded conv of the 10x10 offset fields + clip.
// ---------------------------------------------------------------------------
__global__ void smooth_kernel(const float* __restrict__ ox,
                              const float* __restrict__ oy,
                              const float* __restrict__ w,
                              const int*   __restrict__ mm_raw)
{
    int   mi = mm_raw[0];
    float max_move = (mi > 0 && mi < 1000000) ? (float)mi : __int_as_float(mi);
    float max_offset = 2.0f * max_move / (float)S;

    __shared__ float sw[KW * KW];
    __shared__ float so[G * G];

    int b  = blockIdx.x >> 1;
    int ch = blockIdx.x & 1;
    const float* o = (ch == 0 ? ox : oy) + b * G * G;

    for (int i = threadIdx.x; i < KW * KW; i += blockDim.x) sw[i] = w[i];
    for (int i = threadIdx.x; i < G * G;   i += blockDim.x) so[i] = o[i];
    __syncthreads();

    for (int idx = threadIdx.x; idx < G * G; idx += blockDim.x) {
        int i = idx / G, j = idx % G;
        float acc = 0.0f;
        #pragma unroll
        for (int ky = 0; ky < KW; ky++) {
            int yy = min(max(i + ky - F, 0), G - 1);
            #pragma unroll
            for (int kx = 0; kx < KW; kx++) {
                int xx = min(max(j + kx - F, 0), G - 1);
                acc += so[yy * G + xx] * sw[ky * KW + kx];
            }
        }
        acc *= max_offset;
        acc = fminf(fmaxf(acc, -max_offset), max_offset);
        g_smooth_dev[(b * 2 + ch) * G * G + idx] = acc;
    }
}

// ---------------------------------------------------------------------------
// Kernel 2: fused upsample + grid build + bilinear grid_sample, 3 channels.
// y fixed per block; y-lerp of the field hoisted to shared memory.
// Lane-contiguous pixel mapping (x = xb + tid + p*TPB) for ~128B gather
// footprints. Warp-uniform interior fast path skips masks & clamps.
// ---------------------------------------------------------------------------
__global__ __launch_bounds__(TPB)
void deform_kernel(const float* __restrict__ x, float* __restrict__ out)
{
    const int b   = blockIdx.z;
    const int y   = blockIdx.y;
    const int tid = threadIdx.x;

    __shared__ float rowg[2 * G];   // [0..9] = gx row, [10..19] = gy row

    const float scale = (float)G / (float)S;      // exact
    const float hs    = 0.5f * scale - 0.5f;

    // y-direction field interpolation, once per block
    if (tid < 2 * G) {
        int ch = tid / G;
        int j  = tid - ch * G;
        float sy  = fmaxf(fmaf((float)y, scale, hs), 0.0f);
        int   iy0 = min((int)sy, G - 1);
        int   iy1 = min(iy0 + 1, G - 1);
        float wy  = sy - (float)iy0;
        const float* f = g_smooth_dev + (b * 2 + ch) * G * G;
        float a = f[iy0 * G + j];
        float c = f[iy1 * G + j];
        rowg[tid] = fmaf(c - a, wy, a);
    }
    __syncthreads();

    const float* rowgx = rowg;
    const float* rowgy = rowg + G;

    const int   xb  = blockIdx.x * SPAN;              // 0 or 512
    const float pxs = 2.0f / (float)(S - 1);
    const float pyv = fmaf((float)y, pxs, -1.0f);     // identity grid y

    const float* img = x   + (size_t)b * CC * S * S;
    float*       op  = out + (size_t)b * CC * S * S + (size_t)y * S
                           + xb + tid;

    float r[CC][PX];

    #pragma unroll
    for (int p = 0; p < PX; p++) {
        float xf = (float)(xb + p * TPB + tid);

        // field x-lerp from shared row
        float sx = fmaxf(fmaf(xf, scale, hs), 0.0f);
        int   j0 = min((int)sx, G - 1);
        int   j1 = min(j0 + 1, G - 1);
        float wx = sx - (float)j0;
        float ax0 = rowgx[j0], ax1 = rowgx[j1];
        float ay0 = rowgy[j0], ay1 = rowgy[j1];
        float gx = fmaf(ax1 - ax0, wx, ax0);
        float gy = fmaf(ay1 - ay0, wx, ay0);

        // identity grid + clip
        float g0 = fminf(fmaxf(gx + fmaf(xf, pxs, -1.0f), -1.0f), 1.0f);
        float g1 = fminf(fmaxf(gy + pyv, -1.0f), 1.0f);

        // source coords: ((g+1)*S-1)/2 = g*512 + 511.5, in [-0.5, 1023.5]
        float ixf = fmaf(g0, 512.0f, 511.5f);
        float iyf = fmaf(g1, 512.0f, 511.5f);

        float fx = floorf(ixf), fy = floorf(iyf);
        int x0 = (int)fx, y0 = (int)fy;      // in [-1, 1023]
        float axx = ixf - fx, ayy = iyf - fy;
        float omx = 1.0f - axx, omy = 1.0f - ayy;

        float w00, w01, w10, w11;
        int   o00, o01, o10, o11;

        bool interior = (x0 >= 0) & (x0 < S - 1) & (y0 >= 0) & (y0 < S - 1);
        if (__all_sync(0xffffffffu, interior)) {
            // fast path: no masks, no clamps — ~95% of warps
            w00 = omy * omx;
            w01 = omy * axx;
            w10 = ayy * omx;
            w11 = ayy * axx;
            o00 = (y0 << 10) + x0;
            o01 = o00 + 1;
            o10 = o00 + S;
            o11 = o10 + 1;
        } else {
            float mx0 = (x0 >= 0)    ? 1.0f : 0.0f;
            float mx1 = (x0 < S - 1) ? 1.0f : 0.0f;
            float wy0 = (y0 >= 0)    ? omy  : 0.0f;
            float wy1 = (y0 < S - 1) ? ayy  : 0.0f;
            w00 = wy0 * omx * mx0;
            w01 = wy0 * axx * mx1;
            w10 = wy1 * omx * mx0;
            w11 = wy1 * axx * mx1;
            int xc0 = max(x0, 0);
            int xc1 = min(x0 + 1, S - 1);
            int yc0 = max(y0, 0) << 10;
            int yc1 = min(y0 + 1, S - 1) << 10;
            o00 = yc0 + xc0; o01 = yc0 + xc1;
            o10 = yc1 + xc0; o11 = yc1 + xc1;
        }

        #pragma unroll
        for (int c = 0; c < CC; c++) {
            const float* im = img + (size_t)c * S * S;
            r[c][p] = w00 * __ldg(im + o00) + w01 * __ldg(im + o01)
                    + w10 * __ldg(im + o10) + w11 * __ldg(im + o11);
        }
    }

    // Coalesced stores: 128B warp footprint per store instruction.
    #pragma unroll
    for (int c = 0; c < CC; c++) {
        float* oc = op + (size_t)c * S * S;
        #pragma unroll
        for (int p = 0; p < PX; p++)
            oc[p * TPB] = r[c][p];
    }
}

extern "C" void kernel_launch(void* const* d_in, const int* in_sizes, int n_in,
                              void* d_out, int out_size)
{
    const float* x  = (const float*)d_in[0];
    const float* ox = (const float*)d_in[1];
    const float* oy = (const float*)d_in[2];
    const float* w  = (const float*)d_in[3];
    const int*   mm = (const int*)  d_in[4];

    smooth_kernel<<<BB * 2, 128>>>(ox, oy, w, mm);

    dim3 blk(TPB, 1, 1);
    dim3 grd(S / SPAN, S, BB);   // 2 x 1024 x 8
    deform_kernel<<<grd, blk>>>(x, (float*)d_out);
}